// round 1
// baseline (speedup 1.0000x reference)
#include <cuda_runtime.h>

// cvx_knapsack_solver: batched PGD with knapsack projection via bisection.
// B=16384 rows, N=64 items. 4 threads per row, 16 items per thread (registers).

#define BROWS   16384
#define NITEMS  64
#define TPR     4          // threads per row
#define IPT     16         // items per thread
#define CAPC    102.0f
#define NBIS    60
#define NPGD    120
#define ETAC    0.1f

__device__ __forceinline__ float red4_sum(float v) {
    v += __shfl_xor_sync(0xffffffffu, v, 1);
    v += __shfl_xor_sync(0xffffffffu, v, 2);
    return v;
}
__device__ __forceinline__ float red4_max(float v) {
    v = fmaxf(v, __shfl_xor_sync(0xffffffffu, v, 1));
    v = fmaxf(v, __shfl_xor_sync(0xffffffffu, v, 2));
    return v;
}

// In-place Euclidean projection of the row (distributed across 4 lanes) onto
// {0 <= x <= 1, w@x <= CAPC}. y: this lane's 16 coords. Matches the reference's
// 60-step bisection exactly in structure.
__device__ __forceinline__ void project_ip(float* __restrict__ y,
                                           const float* __restrict__ w,
                                           const float* __restrict__ rw) {
    // g(0) for feasibility test + upper bracket hi = max(relu(y)/w) + 1e-3
    float s0 = 0.0f, hm = 0.0f;
#pragma unroll
    for (int i = 0; i < IPT; i++) {
        float yp = fmaxf(y[i], 0.0f);
        s0 = fmaf(fminf(yp, 1.0f), w[i], s0);
        hm = fmaxf(hm, yp * rw[i]);
    }
    s0 = red4_sum(s0);
    hm = red4_max(hm);

    float lo = 0.0f, hi = hm + 1e-3f;
#pragma unroll 1
    for (int it = 0; it < NBIS; it++) {
        float mid = 0.5f * (lo + hi);
        float s = 0.0f;
#pragma unroll
        for (int i = 0; i < IPT; i++) {
            float z = fmaf(-mid, w[i], y[i]);
            z = fminf(fmaxf(z, 0.0f), 1.0f);
            s = fmaf(z, w[i], s);
        }
        s = red4_sum(s);
        bool over = s > CAPC;
        lo = over ? mid : lo;
        hi = over ? hi : mid;
    }
    float lam = 0.5f * (lo + hi);
    if (s0 <= CAPC) lam = 0.0f;   // constraint inactive at lam=0

#pragma unroll
    for (int i = 0; i < IPT; i++) {
        float z = fmaf(-lam, w[i], y[i]);
        y[i] = fminf(fmaxf(z, 0.0f), 1.0f);
    }
}

__global__ void __launch_bounds__(128)
cvx_knapsack_kernel(const float* __restrict__ costs,
                    const float* __restrict__ wg,
                    float* __restrict__ out) {
    int tid = blockIdx.x * blockDim.x + threadIdx.x;
    int row = tid >> 2;
    int q   = tid & 3;
    if (row >= BROWS) return;

    float w[IPT], rw[IPT], c[IPT], x[IPT];

    const float4* cp = reinterpret_cast<const float4*>(costs + row * NITEMS + q * IPT);
    const float4* wp = reinterpret_cast<const float4*>(wg + q * IPT);
#pragma unroll
    for (int j = 0; j < IPT / 4; j++) {
        float4 cv = cp[j];
        float4 wv = wp[j];
        c[4*j+0] = cv.x; c[4*j+1] = cv.y; c[4*j+2] = cv.z; c[4*j+3] = cv.w;
        w[4*j+0] = wv.x; w[4*j+1] = wv.y; w[4*j+2] = wv.z; w[4*j+3] = wv.w;
    }
#pragma unroll
    for (int i = 0; i < IPT; i++) rw[i] = 1.0f / w[i];

    // x = project(clip(costs, 0, 1))
#pragma unroll
    for (int i = 0; i < IPT; i++) x[i] = fminf(fmaxf(c[i], 0.0f), 1.0f);
    project_ip(x, w, rw);

    // 120 PGD steps: grad = c - x/||x||;  x = project(x + eta*grad)
#pragma unroll 1
    for (int t = 0; t < NPGD; t++) {
        float ss = 0.0f;
#pragma unroll
        for (int i = 0; i < IPT; i++) ss = fmaf(x[i], x[i], ss);
        ss = red4_sum(ss);
        float inv = rsqrtf(ss + 1e-12f);   // 1/nrm
#pragma unroll
        for (int i = 0; i < IPT; i++) {
            float g = fmaf(-x[i], inv, c[i]);   // c - x/nrm (MU = 1)
            x[i] = fmaf(ETAC, g, x[i]);
        }
        project_ip(x, w, rw);
    }

    float4* op = reinterpret_cast<float4*>(out + row * NITEMS + q * IPT);
#pragma unroll
    for (int j = 0; j < IPT / 4; j++) {
        float4 v;
        v.x = x[4*j+0]; v.y = x[4*j+1]; v.z = x[4*j+2]; v.w = x[4*j+3];
        op[j] = v;
    }
}

extern "C" void kernel_launch(void* const* d_in, const int* in_sizes, int n_in,
                              void* d_out, int out_size) {
    const float* costs = (const float*)d_in[0];
    const float* wts   = (const float*)d_in[1];
    // metadata order: costs [16384*64], weights [64]. Guard on sizes anyway.
    if (n_in >= 2 && in_sizes[0] == NITEMS) {
        costs = (const float*)d_in[1];
        wts   = (const float*)d_in[0];
    }
    float* out = (float*)d_out;

    const int threads = 128;
    const int total   = BROWS * TPR;
    const int blocks  = (total + threads - 1) / threads;   // 512
    cvx_knapsack_kernel<<<blocks, threads>>>(costs, wts, out);
}

// round 2
// speedup vs baseline: 2.9453x; 2.9453x over previous
#include <cuda_runtime.h>

// cvx_knapsack_solver: batched PGD with knapsack projection.
// Projection root-find g(lam)=CAP via safeguarded false position (Illinois),
// 1 eval at lam=0 (feasibility) + NIT Illinois iterations.
// Layout: 8 threads per row, 8 items per thread, all state in registers.

#define BROWS   16384
#define NITEMS  64
#define TPR     8          // threads per row
#define IPT     8          // items per thread
#define CAPC    102.0f
#define NPGD    120
#define ETAC    0.1f
#define NIT     12         // Illinois iterations (after the lam=0 eval)
#define HI0     2.0f       // g(HI0)=0 guaranteed: y <= ~1.65, w >= 1

__device__ __forceinline__ float red8_sum(float v) {
    v += __shfl_xor_sync(0xffffffffu, v, 1);
    v += __shfl_xor_sync(0xffffffffu, v, 2);
    v += __shfl_xor_sync(0xffffffffu, v, 4);
    return v;
}

// g(m) = sum_i w_i * clip(y_i - m*w_i, 0, 1), reduced across the 8 lanes of a row.
// Two independent accumulators shorten the FFMA dependency chain.
__device__ __forceinline__ float evalg(const float* __restrict__ y,
                                       const float* __restrict__ w,
                                       float m) {
    float sa = 0.0f, sb = 0.0f;
#pragma unroll
    for (int i = 0; i < IPT; i += 2) {
        float za = fmaf(-m, w[i],     y[i]);
        float zb = fmaf(-m, w[i + 1], y[i + 1]);
        za = fminf(fmaxf(za, 0.0f), 1.0f);
        zb = fminf(fmaxf(zb, 0.0f), 1.0f);
        sa = fmaf(za, w[i],     sa);
        sb = fmaf(zb, w[i + 1], sb);
    }
    return red8_sum(sa + sb);
}

// Projection of row (split across 8 lanes) onto {0<=x<=1, w@x<=CAPC}, in place.
__device__ __forceinline__ void project_ip(float* __restrict__ y,
                                           const float* __restrict__ w) {
    // Eval at 0: feasibility test + lower bracket value.
    float s0 = evalg(y, w, 0.0f);
    bool  feas = (s0 <= CAPC);

    float lo = 0.0f,  fl = s0 - CAPC;   // fl > 0 when active
    float hi = HI0,   fh = -CAPC;       // g(HI0) = 0 exactly
    bool  prev_over = false;            // last updated side was lo?

#pragma unroll 1
    for (int it = 0; it < NIT; it++) {
        // False-position point: fl > 0 > fh keeps mid strictly inside (lo,hi).
        float mid = lo + fl * __fdividef(hi - lo, fl - fh);
        float f = evalg(y, w, mid) - CAPC;
        bool over = f > 0.0f;
        // Illinois: halve the retained endpoint's f when the same side repeats.
        float fh_n = over ? (prev_over ? 0.5f * fh : fh) : f;
        float fl_n = over ? f : (prev_over ? fl : 0.5f * fl);
        lo = over ? mid : lo;
        hi = over ? hi : mid;
        fl = fl_n; fh = fh_n;
        prev_over = over;
    }
    float lam = lo + fl * __fdividef(hi - lo, fl - fh);
    lam = feas ? 0.0f : lam;

#pragma unroll
    for (int i = 0; i < IPT; i++) {
        float z = fmaf(-lam, w[i], y[i]);
        y[i] = fminf(fmaxf(z, 0.0f), 1.0f);
    }
}

__global__ void __launch_bounds__(256)
cvx_knapsack_kernel(const float* __restrict__ costs,
                    const float* __restrict__ wg,
                    float* __restrict__ out) {
    int tid = blockIdx.x * blockDim.x + threadIdx.x;
    int row = tid >> 3;
    int q   = tid & 7;
    if (row >= BROWS) return;

    float w[IPT], c[IPT], x[IPT];

    const float4* cp = reinterpret_cast<const float4*>(costs + row * NITEMS + q * IPT);
    const float4* wp = reinterpret_cast<const float4*>(wg + q * IPT);
#pragma unroll
    for (int j = 0; j < IPT / 4; j++) {
        float4 cv = cp[j];
        float4 wv = wp[j];
        c[4*j+0] = cv.x; c[4*j+1] = cv.y; c[4*j+2] = cv.z; c[4*j+3] = cv.w;
        w[4*j+0] = wv.x; w[4*j+1] = wv.y; w[4*j+2] = wv.z; w[4*j+3] = wv.w;
    }

    // x = project(clip(costs, 0, 1))
#pragma unroll
    for (int i = 0; i < IPT; i++) x[i] = fminf(fmaxf(c[i], 0.0f), 1.0f);
    project_ip(x, w);

    // 120 PGD steps: grad = c - x/||x||;  x = project(x + eta*grad)
#pragma unroll 1
    for (int t = 0; t < NPGD; t++) {
        float sa = 0.0f, sb = 0.0f;
#pragma unroll
        for (int i = 0; i < IPT; i += 2) {
            sa = fmaf(x[i],     x[i],     sa);
            sb = fmaf(x[i + 1], x[i + 1], sb);
        }
        float ss = red8_sum(sa + sb);
        float inv = rsqrtf(ss + 1e-12f);   // 1/||x||
#pragma unroll
        for (int i = 0; i < IPT; i++) {
            float g = fmaf(-x[i], inv, c[i]);   // c - x/nrm  (MU = 1)
            x[i] = fmaf(ETAC, g, x[i]);
        }
        project_ip(x, w);
    }

    float4* op = reinterpret_cast<float4*>(out + row * NITEMS + q * IPT);
#pragma unroll
    for (int j = 0; j < IPT / 4; j++) {
        float4 v;
        v.x = x[4*j+0]; v.y = x[4*j+1]; v.z = x[4*j+2]; v.w = x[4*j+3];
        op[j] = v;
    }
}

extern "C" void kernel_launch(void* const* d_in, const int* in_sizes, int n_in,
                              void* d_out, int out_size) {
    const float* costs = (const float*)d_in[0];
    const float* wts   = (const float*)d_in[1];
    if (n_in >= 2 && in_sizes[0] == NITEMS) {   // guard against input order swap
        costs = (const float*)d_in[1];
        wts   = (const float*)d_in[0];
    }
    float* out = (float*)d_out;

    const int threads = 256;
    const int total   = BROWS * TPR;
    const int blocks  = (total + threads - 1) / threads;   // 512
    cvx_knapsack_kernel<<<blocks, threads>>>(costs, wts, out);
}

// round 3
// speedup vs baseline: 5.8911x; 2.0002x over previous
#include <cuda_runtime.h>

// cvx_knapsack_solver: batched PGD with knapsack projection.
// Projection root-find g(lam)=CAP via warm-started, bracket-safeguarded Newton
// on the piecewise-linear g (exact once the iterate reaches the root's segment).
// Layout: 8 threads per row, 8 items per thread, all state in registers.

#define BROWS   16384
#define NITEMS  64
#define TPR     8          // threads per row
#define IPT     8          // items per thread
#define CAPC    102.0f
#define NPGD    120
#define ETAC    0.1f
#define NIT0    6          // Newton evals, cold first projection
#define NIT     3          // Newton evals, warm-started projections
#define HI0     2.0f       // g(HI0)=0 guaranteed: y <= ~1.6, w >= 1

// f(m) = g(m) - CAP and d(m) = -g'(m) = sum_{interior} w^2, reduced over 8 lanes.
__device__ __forceinline__ void evalgd(const float* __restrict__ y,
                                       const float* __restrict__ w,
                                       const float* __restrict__ w2,
                                       float m, float& f, float& d) {
    float sa = 0.0f, sb = 0.0f, da = 0.0f, db = 0.0f;
#pragma unroll
    for (int i = 0; i < IPT; i += 2) {
        float za = fmaf(-m, w[i],     y[i]);
        float zb = fmaf(-m, w[i + 1], y[i + 1]);
        float ca = fminf(fmaxf(za, 0.0f), 1.0f);
        float cb = fminf(fmaxf(zb, 0.0f), 1.0f);
        sa = fmaf(ca, w[i],     sa);
        sb = fmaf(cb, w[i + 1], sb);
        da += (za > 0.0f && za < 1.0f) ? w2[i]     : 0.0f;
        db += (zb > 0.0f && zb < 1.0f) ? w2[i + 1] : 0.0f;
    }
    float s  = sa + sb;
    float dd = da + db;
#pragma unroll
    for (int k = 1; k < TPR; k <<= 1) {
        s  += __shfl_xor_sync(0xffffffffu, s,  k);
        dd += __shfl_xor_sync(0xffffffffu, dd, k);
    }
    f = s - CAPC;
    d = dd;
}

// In-place projection of the row onto {0<=x<=1, w@x<=CAPC}. Returns lam for
// warm-starting the next projection. Clamping the Newton proposal to lo=0
// subsumes the reference's lam=0 feasibility branch: any eval at 0 with
// f(0)<=0 pins hi=0 and hence lam=0.
__device__ __forceinline__ float project_ip(float* __restrict__ y,
                                            const float* __restrict__ w,
                                            const float* __restrict__ w2,
                                            float lam, int nit) {
    float lo = 0.0f, hi = HI0;
#pragma unroll 1
    for (int it = 0; it < nit; it++) {
        float f, d;
        evalgd(y, w, w2, lam, f, d);
        bool over = f > 0.0f;           // lam too small
        lo = over ? lam : lo;
        hi = over ? hi  : lam;
        float ln = lam + __fdividef(f, d);   // Newton (g decreasing: slope -d)
        ln = fmaxf(ln, lo);             // NaN-safe: fmaxf(NaN,lo)=lo
        ln = fminf(ln, hi);
        lam = ln;
    }
#pragma unroll
    for (int i = 0; i < IPT; i++) {
        float z = fmaf(-lam, w[i], y[i]);
        y[i] = fminf(fmaxf(z, 0.0f), 1.0f);
    }
    return lam;
}

__global__ void __launch_bounds__(256)
cvx_knapsack_kernel(const float* __restrict__ costs,
                    const float* __restrict__ wg,
                    float* __restrict__ out) {
    int tid = blockIdx.x * blockDim.x + threadIdx.x;
    int row = tid >> 3;
    int q   = tid & 7;
    if (row >= BROWS) return;

    float w[IPT], w2[IPT], c[IPT], x[IPT];

    const float4* cp = reinterpret_cast<const float4*>(costs + row * NITEMS + q * IPT);
    const float4* wp = reinterpret_cast<const float4*>(wg + q * IPT);
#pragma unroll
    for (int j = 0; j < IPT / 4; j++) {
        float4 cv = cp[j];
        float4 wv = wp[j];
        c[4*j+0] = cv.x; c[4*j+1] = cv.y; c[4*j+2] = cv.z; c[4*j+3] = cv.w;
        w[4*j+0] = wv.x; w[4*j+1] = wv.y; w[4*j+2] = wv.z; w[4*j+3] = wv.w;
    }
#pragma unroll
    for (int i = 0; i < IPT; i++) w2[i] = w[i] * w[i];

    // x = project(clip(costs, 0, 1)), cold start
#pragma unroll
    for (int i = 0; i < IPT; i++) x[i] = fminf(fmaxf(c[i], 0.0f), 1.0f);
    float lam = project_ip(x, w, w2, 0.0f, NIT0);

    // 120 PGD steps: grad = c - x/||x||;  x = project(x + eta*grad), warm lam
#pragma unroll 1
    for (int t = 0; t < NPGD; t++) {
        float sa = 0.0f, sb = 0.0f;
#pragma unroll
        for (int i = 0; i < IPT; i += 2) {
            sa = fmaf(x[i],     x[i],     sa);
            sb = fmaf(x[i + 1], x[i + 1], sb);
        }
        float ss = sa + sb;
#pragma unroll
        for (int k = 1; k < TPR; k <<= 1)
            ss += __shfl_xor_sync(0xffffffffu, ss, k);
        float inv = rsqrtf(ss + 1e-12f);   // 1/||x||
#pragma unroll
        for (int i = 0; i < IPT; i++) {
            float g = fmaf(-x[i], inv, c[i]);   // c - x/nrm  (MU = 1)
            x[i] = fmaf(ETAC, g, x[i]);
        }
        lam = project_ip(x, w, w2, lam, NIT);
    }

    float4* op = reinterpret_cast<float4*>(out + row * NITEMS + q * IPT);
#pragma unroll
    for (int j = 0; j < IPT / 4; j++) {
        float4 v;
        v.x = x[4*j+0]; v.y = x[4*j+1]; v.z = x[4*j+2]; v.w = x[4*j+3];
        op[j] = v;
    }
}

extern "C" void kernel_launch(void* const* d_in, const int* in_sizes, int n_in,
                              void* d_out, int out_size) {
    const float* costs = (const float*)d_in[0];
    const float* wts   = (const float*)d_in[1];
    if (n_in >= 2 && in_sizes[0] == NITEMS) {   // guard against input order swap
        costs = (const float*)d_in[1];
        wts   = (const float*)d_in[0];
    }
    float* out = (float*)d_out;

    const int threads = 256;
    const int total   = BROWS * TPR;
    const int blocks  = (total + threads - 1) / threads;   // 512
    cvx_knapsack_kernel<<<blocks, threads>>>(costs, wts, out);
}

// round 4
// speedup vs baseline: 8.0094x; 1.3596x over previous
#include <cuda_runtime.h>

// cvx_knapsack_solver: batched PGD + knapsack projection (warm-started
// safeguarded Newton on piecewise-linear g). sm_103a: packed f32x2 FMAs.
// Layout: 8 threads/row, 8 items/thread (4 float2 pairs), all in registers.

#define BROWS   16384
#define NITEMS  64
#define TPR     8
#define IPT     8
#define NPAIR   4          // IPT/2 float2 pairs
#define CAPC    102.0f
#define NPGD    120
#define ETAC    0.1f
#define NIT0    6          // Newton evals, cold first projection
#define NIT     3          // Newton evals, warm-started projections
#define HI0     2.0f       // g(HI0)=0 guaranteed: y <= ~1.6, w >= 1

// Packed dual-fp32 FMA (Blackwell FFMA2). mov.b64 is register pairing only.
__device__ __forceinline__ float2 fma2(float2 a, float2 b, float2 c) {
    float2 r;
    asm("{\n\t"
        ".reg .b64 ra, rb, rc, rd;\n\t"
        "mov.b64 ra, {%2, %3};\n\t"
        "mov.b64 rb, {%4, %5};\n\t"
        "mov.b64 rc, {%6, %7};\n\t"
        "fma.rn.f32x2 rd, ra, rb, rc;\n\t"
        "mov.b64 {%0, %1}, rd;\n\t"
        "}"
        : "=f"(r.x), "=f"(r.y)
        : "f"(a.x), "f"(a.y), "f"(b.x), "f"(b.y), "f"(c.x), "f"(c.y));
    return r;
}

// 1.0f if a==b else 0.0f (single FSET; avoids FSETP+FSEL chains).
__device__ __forceinline__ float seteqf(float a, float b) {
    float r;
    asm("set.eq.f32.f32 %0, %1, %2;" : "=f"(r) : "f"(a), "f"(b));
    return r;
}

// f(m) = g(m) - CAP; d(m) = sum_{interior} w^2. Reduced over the row's 8 lanes.
// Interior indicator: clip(z)==z (kink ties harmless under bracket safeguard).
__device__ __forceinline__ void evalgd(const float2* __restrict__ y,
                                       const float2* __restrict__ w,
                                       const float2* __restrict__ w2,
                                       float m, float& f, float& d) {
    float2 mm = make_float2(-m, -m);
    float2 s  = make_float2(0.f, 0.f);
    float2 dv = make_float2(0.f, 0.f);
#pragma unroll
    for (int j = 0; j < NPAIR; j++) {
        float2 z = fma2(mm, w[j], y[j]);
        float2 h;
        h.x = fminf(fmaxf(z.x, 0.f), 1.f);
        h.y = fminf(fmaxf(z.y, 0.f), 1.f);
        s = fma2(h, w[j], s);
        float2 ind;
        ind.x = seteqf(h.x, z.x);
        ind.y = seteqf(h.y, z.y);
        dv = fma2(ind, w2[j], dv);
    }
    float sf = s.x + s.y;
    float df = dv.x + dv.y;
#pragma unroll
    for (int k = 1; k < TPR; k <<= 1) {
        sf += __shfl_xor_sync(0xffffffffu, sf, k);
        df += __shfl_xor_sync(0xffffffffu, df, k);
    }
    f = sf - CAPC;
    d = df;
}

// In-place projection onto {0<=x<=1, w@x<=CAPC}; returns lam for warm start.
// Clamping Newton into [0, HI0] subsumes the lam=0 feasibility branch.
__device__ __forceinline__ float project_ip(float2* __restrict__ y,
                                            const float2* __restrict__ w,
                                            const float2* __restrict__ w2,
                                            float lam, int nit) {
    float lo = 0.f, hi = HI0;
#pragma unroll 1
    for (int it = 0; it < nit; it++) {
        float f, d;
        evalgd(y, w, w2, lam, f, d);
        bool over = f > 0.f;            // lam too small
        lo = over ? lam : lo;
        hi = over ? hi  : lam;
        float ln = lam + __fdividef(f, d);
        ln = fmaxf(ln, lo);             // NaN-safe: fmaxf(NaN,lo)=lo
        ln = fminf(ln, hi);
        lam = ln;
    }
    float2 ml = make_float2(-lam, -lam);
#pragma unroll
    for (int j = 0; j < NPAIR; j++) {
        float2 z = fma2(ml, w[j], y[j]);
        y[j].x = fminf(fmaxf(z.x, 0.f), 1.f);
        y[j].y = fminf(fmaxf(z.y, 0.f), 1.f);
    }
    return lam;
}

__global__ void __launch_bounds__(128)
cvx_knapsack_kernel(const float* __restrict__ costs,
                    const float* __restrict__ wg,
                    float* __restrict__ out) {
    int tid = blockIdx.x * blockDim.x + threadIdx.x;
    int row = tid >> 3;
    int q   = tid & 7;
    if (row >= BROWS) return;

    float2 w[NPAIR], w2[NPAIR], c[NPAIR], x[NPAIR];

    const float4* cp = reinterpret_cast<const float4*>(costs + row * NITEMS + q * IPT);
    const float4* wp = reinterpret_cast<const float4*>(wg + q * IPT);
#pragma unroll
    for (int j = 0; j < NPAIR / 2; j++) {
        float4 cv = cp[j];
        float4 wv = wp[j];
        c[2*j]     = make_float2(cv.x, cv.y);
        c[2*j + 1] = make_float2(cv.z, cv.w);
        w[2*j]     = make_float2(wv.x, wv.y);
        w[2*j + 1] = make_float2(wv.z, wv.w);
    }
#pragma unroll
    for (int j = 0; j < NPAIR; j++)
        w2[j] = make_float2(w[j].x * w[j].x, w[j].y * w[j].y);

    // x = project(clip(costs, 0, 1)), cold start
#pragma unroll
    for (int j = 0; j < NPAIR; j++) {
        x[j].x = fminf(fmaxf(c[j].x, 0.f), 1.f);
        x[j].y = fminf(fmaxf(c[j].y, 0.f), 1.f);
    }
    float lam = project_ip(x, w, w2, 0.0f, NIT0);

    // 120 PGD steps: x = project(x + eta*(c - x/||x||)), warm-started lam.
#pragma unroll 1
    for (int t = 0; t < NPGD; t++) {
        float2 acc = make_float2(0.f, 0.f);
#pragma unroll
        for (int j = 0; j < NPAIR; j++) acc = fma2(x[j], x[j], acc);
        float ss = acc.x + acc.y;
#pragma unroll
        for (int k = 1; k < TPR; k <<= 1)
            ss += __shfl_xor_sync(0xffffffffu, ss, k);
        float inv = rsqrtf(ss + 1e-12f);        // 1/||x||
        float2 ee = make_float2(ETAC, ETAC);
        float2 aa = make_float2(-ETAC * inv, -ETAC * inv);
#pragma unroll
        for (int j = 0; j < NPAIR; j++)
            x[j] = fma2(aa, x[j], fma2(ee, c[j], x[j]));   // x + eta*c - eta*inv*x
        lam = project_ip(x, w, w2, lam, NIT);
    }

    float4* op = reinterpret_cast<float4*>(out + row * NITEMS + q * IPT);
#pragma unroll
    for (int j = 0; j < NPAIR / 2; j++) {
        float4 v;
        v.x = x[2*j].x;     v.y = x[2*j].y;
        v.z = x[2*j + 1].x; v.w = x[2*j + 1].y;
        op[j] = v;
    }
}

extern "C" void kernel_launch(void* const* d_in, const int* in_sizes, int n_in,
                              void* d_out, int out_size) {
    const float* costs = (const float*)d_in[0];
    const float* wts   = (const float*)d_in[1];
    if (n_in >= 2 && in_sizes[0] == NITEMS) {   // guard against input order swap
        costs = (const float*)d_in[1];
        wts   = (const float*)d_in[0];
    }
    float* out = (float*)d_out;

    // 128-thread blocks: 1024 blocks over 152 SMs (~6.7/SM) for wave balance.
    const int threads = 128;
    const int total   = BROWS * TPR;
    const int blocks  = (total + threads - 1) / threads;   // 1024
    cvx_knapsack_kernel<<<blocks, threads>>>(costs, wts, out);
}

// round 6
// speedup vs baseline: 12.6430x; 1.5785x over previous
#include <cuda_runtime.h>

// cvx_knapsack_solver: batched PGD + knapsack projection.
// Projection: warm-started, bracket-safeguarded SECANT on the piecewise-linear
// g(lam) (derivative-free; exact once two iterates share the root's segment).
// Carries reciprocal slope across projections. sm_103a packed f32x2 FMAs.
// Layout: 8 lanes per row, 8 items per lane, 2 independent rows per thread
// (w is row-invariant) for ILP across the serial shuffle/MUFU chains.

#define BROWS   16384
#define NITEMS  64
#define TPR     8
#define IPT     8
#define NPAIR   4          // IPT/2 float2 pairs
#define CAPC    102.0f
#define NPGD    120
#define ETAC    0.1f
#define NIT0    8          // secant evals, cold first projection
#define NIT     2          // secant evals, warm-started projections
#define HI0     2.0f       // g(HI0)=0 guaranteed: y <= ~1.6, w >= 1

// Packed dual-fp32 FMA (Blackwell FFMA2). mov.b64 is register pairing only.
__device__ __forceinline__ float2 fma2(float2 a, float2 b, float2 c) {
    float2 r;
    asm("{\n\t"
        ".reg .b64 ra, rb, rc, rd;\n\t"
        "mov.b64 ra, {%2, %3};\n\t"
        "mov.b64 rb, {%4, %5};\n\t"
        "mov.b64 rc, {%6, %7};\n\t"
        "fma.rn.f32x2 rd, ra, rb, rc;\n\t"
        "mov.b64 {%0, %1}, rd;\n\t"
        "}"
        : "=f"(r.x), "=f"(r.y)
        : "f"(a.x), "f"(a.y), "f"(b.x), "f"(b.y), "f"(c.x), "f"(c.y));
    return r;
}

__device__ __forceinline__ float red8(float v) {
    v += __shfl_xor_sync(0xffffffffu, v, 1);
    v += __shfl_xor_sync(0xffffffffu, v, 2);
    v += __shfl_xor_sync(0xffffffffu, v, 4);
    return v;
}

// f[r] = g_r(lam[r]) - CAP for both rows, reduced over each row's 8 lanes.
// The two rows' chains are independent and interleave.
__device__ __forceinline__ void evalg2(const float2 x[2][NPAIR],
                                       const float2 w[NPAIR],
                                       const float lam[2], float f[2]) {
    float2 m0 = make_float2(-lam[0], -lam[0]);
    float2 m1 = make_float2(-lam[1], -lam[1]);
    float2 s0 = make_float2(0.f, 0.f);
    float2 s1 = make_float2(0.f, 0.f);
#pragma unroll
    for (int j = 0; j < NPAIR; j++) {
        float2 z0 = fma2(m0, w[j], x[0][j]);
        float2 z1 = fma2(m1, w[j], x[1][j]);
        z0.x = fminf(fmaxf(z0.x, 0.f), 1.f);
        z0.y = fminf(fmaxf(z0.y, 0.f), 1.f);
        z1.x = fminf(fmaxf(z1.x, 0.f), 1.f);
        z1.y = fminf(fmaxf(z1.y, 0.f), 1.f);
        s0 = fma2(z0, w[j], s0);
        s1 = fma2(z1, w[j], s1);
    }
    f[0] = red8(s0.x + s0.y) - CAPC;
    f[1] = red8(s1.x + s1.y) - CAPC;
}

// In-place projection of both rows onto {0<=x<=1, w@x<=CAPC}.
// lam: warm-start multipliers (updated). rdch: cached reciprocal slopes
// 1/(-g') (updated). Bracket clamp into [0, HI0] subsumes the lam=0
// feasibility branch of the reference.
template <int NITER>
__device__ __forceinline__ void project2(float2 x[2][NPAIR],
                                         const float2 w[NPAIR],
                                         float lam[2], float rdch[2]) {
    float lo[2] = {0.f, 0.f}, hi[2] = {HI0, HI0};
    float lamp[2], fp[2];
#pragma unroll
    for (int it = 0; it < NITER; it++) {
        float f[2];
        evalg2(x, w, lam, f);
#pragma unroll
        for (int r = 0; r < 2; r++) {
            bool over = f[r] > 0.f;                 // lam too small
            lo[r] = over ? lam[r] : lo[r];
            hi[r] = over ? hi[r]  : lam[r];
            float rdd;
            if (it == 0) {
                rdd = rdch[r];                      // cached from last projection
            } else {
                // reciprocal secant slope; g decreasing => rds > 0 when valid
                float rds = __fdividef(lam[r] - lamp[r], fp[r] - f[r]);
                rdd = (rds > 0.f && rds < 1e12f) ? rds : rdch[r];
            }
            lamp[r] = lam[r];
            fp[r]   = f[r];
            float ln = fmaf(f[r], rdd, lam[r]);     // secant/Newton step
            ln = fmaxf(ln, lo[r]);                  // NaN-safe clamps
            ln = fminf(ln, hi[r]);
            lam[r]  = ln;
            rdch[r] = rdd;
        }
    }
#pragma unroll
    for (int r = 0; r < 2; r++) {
        float2 ml = make_float2(-lam[r], -lam[r]);
#pragma unroll
        for (int j = 0; j < NPAIR; j++) {
            float2 z = fma2(ml, w[j], x[r][j]);
            x[r][j].x = fminf(fmaxf(z.x, 0.f), 1.f);
            x[r][j].y = fminf(fmaxf(z.y, 0.f), 1.f);
        }
    }
}

__global__ void __launch_bounds__(64)
cvx_knapsack_kernel(const float* __restrict__ costs,
                    const float* __restrict__ wg,
                    float* __restrict__ out) {
    int tid  = blockIdx.x * blockDim.x + threadIdx.x;
    int q    = tid & 7;          // lane within row group
    int pair = tid >> 3;         // handles rows 2*pair, 2*pair+1
    int row0 = pair * 2;
    if (row0 >= BROWS) return;

    float2 w[NPAIR], ec[2][NPAIR], x[2][NPAIR];

    const float4* wp = reinterpret_cast<const float4*>(wg + q * IPT);
#pragma unroll
    for (int j = 0; j < NPAIR / 2; j++) {
        float4 wv = wp[j];
        w[2*j]     = make_float2(wv.x, wv.y);
        w[2*j + 1] = make_float2(wv.z, wv.w);
    }

#pragma unroll
    for (int r = 0; r < 2; r++) {
        const float4* cp = reinterpret_cast<const float4*>(
            costs + (row0 + r) * NITEMS + q * IPT);
#pragma unroll
        for (int j = 0; j < NPAIR / 2; j++) {
            float4 cv = cp[j];
            float2 c0 = make_float2(cv.x, cv.y);
            float2 c1 = make_float2(cv.z, cv.w);
            // x = clip(c, 0, 1); keep eta*c for the fused PGD update
            x[r][2*j].x = fminf(fmaxf(c0.x, 0.f), 1.f);
            x[r][2*j].y = fminf(fmaxf(c0.y, 0.f), 1.f);
            x[r][2*j+1].x = fminf(fmaxf(c1.x, 0.f), 1.f);
            x[r][2*j+1].y = fminf(fmaxf(c1.y, 0.f), 1.f);
            ec[r][2*j]   = make_float2(ETAC * c0.x, ETAC * c0.y);
            ec[r][2*j+1] = make_float2(ETAC * c1.x, ETAC * c1.y);
        }
    }

    float lam[2]  = {0.f, 0.f};
    float rdch[2] = {1.0f / 1000.0f, 1.0f / 1000.0f};  // ~1/Sum_interior w^2
    project2<NIT0>(x, w, lam, rdch);

    // 120 PGD steps: x = project(k*x + eta*c), k = 1 - eta/||x||  (MU = 1)
#pragma unroll 1
    for (int t = 0; t < NPGD; t++) {
#pragma unroll
        for (int r = 0; r < 2; r++) {
            float2 acc = make_float2(0.f, 0.f);
#pragma unroll
            for (int j = 0; j < NPAIR; j++) acc = fma2(x[r][j], x[r][j], acc);
            float ss  = red8(acc.x + acc.y);
            float inv = rsqrtf(ss + 1e-12f);
            float k   = fmaf(-ETAC, inv, 1.0f);
            float2 kk = make_float2(k, k);
#pragma unroll
            for (int j = 0; j < NPAIR; j++)
                x[r][j] = fma2(kk, x[r][j], ec[r][j]);
        }
        project2<NIT>(x, w, lam, rdch);
    }

#pragma unroll
    for (int r = 0; r < 2; r++) {
        float4* op = reinterpret_cast<float4*>(out + (row0 + r) * NITEMS + q * IPT);
#pragma unroll
        for (int j = 0; j < NPAIR / 2; j++) {
            float4 v;
            v.x = x[r][2*j].x;     v.y = x[r][2*j].y;
            v.z = x[r][2*j + 1].x; v.w = x[r][2*j + 1].y;
            op[j] = v;
        }
    }
}

extern "C" void kernel_launch(void* const* d_in, const int* in_sizes, int n_in,
                              void* d_out, int out_size) {
    const float* costs = (const float*)d_in[0];
    const float* wts   = (const float*)d_in[1];
    if (n_in >= 2 && in_sizes[0] == NITEMS) {   // guard against input order swap
        costs = (const float*)d_in[1];
        wts   = (const float*)d_in[0];
    }
    float* out = (float*)d_out;

    const int threads = 64;
    const int total   = (BROWS / 2) * TPR;                 // 65536 threads
    const int blocks  = (total + threads - 1) / threads;   // 1024 blocks
    cvx_knapsack_kernel<<<blocks, threads>>>(costs, wts, out);
}

// round 9
// speedup vs baseline: 13.9441x; 1.1029x over previous
#include <cuda_runtime.h>

// cvx_knapsack_solver: batched PGD + knapsack projection (R6 algorithm:
// warm-started 2-eval within-projection secant on piecewise-linear g,
// bracket-clamped to [0,2]; slope cached across projections only as the
// initial guess, corrected within each projection).
// This round: split-lane reductions (3 SHFL per row-pair) + lane-parallel
// scalar chains (lanes 0-3 of each 8-lane group own row0, lanes 4-7 row1)
// + norm fused into the projection apply. Proven instructions only.

#define BROWS   16384
#define NITEMS  64
#define TPR     8
#define IPT     8
#define NPAIR   4          // IPT/2 float2 pairs
#define CAPC    102.0f
#define NPGD    120
#define ETAC    0.1f
#define NIT0    8          // secant evals, cold first projection
#define NIT     2          // secant evals, warm-started projections
#define HI0     2.0f       // g(HI0)=0 guaranteed: y <= ~1.6, w >= 1

// Packed dual-fp32 FMA (Blackwell FFMA2). mov.b64 is register pairing only.
__device__ __forceinline__ float2 fma2(float2 a, float2 b, float2 c) {
    float2 r;
    asm("{\n\t"
        ".reg .b64 ra, rb, rc, rd;\n\t"
        "mov.b64 ra, {%2, %3};\n\t"
        "mov.b64 rb, {%4, %5};\n\t"
        "mov.b64 rc, {%6, %7};\n\t"
        "fma.rn.f32x2 rd, ra, rb, rc;\n\t"
        "mov.b64 {%0, %1}, rd;\n\t"
        "}"
        : "=f"(r.x), "=f"(r.y)
        : "f"(a.x), "f"(a.y), "f"(b.x), "f"(b.y), "f"(c.x), "f"(c.y));
    return r;
}

__device__ __forceinline__ float2 clip01(float2 z) {
    z.x = fminf(fmaxf(z.x, 0.f), 1.f);
    z.y = fminf(fmaxf(z.y, 0.f), 1.f);
    return z;
}

// Split reduction over an 8-lane group carrying two values (one per row):
// returns the total of MY row (row0 for lanes 0-3 of the group, row1 for 4-7).
// 3 shuffles total for both rows (vs 6 with two full trees).
__device__ __forceinline__ float red8_split(float s0, float s1, bool hb) {
    float v = hb ? s0 : s1;                         // send what partner needs
    float u = __shfl_xor_sync(0xffffffffu, v, 4);
    float t = (hb ? s1 : s0) + u;                   // my row, both halves
    t += __shfl_xor_sync(0xffffffffu, t, 1);
    t += __shfl_xor_sync(0xffffffffu, t, 2);
    return t;
}

// f_mine = g_{my row}(lam_{my row}) - CAP. Both rows' FMA chains interleave.
__device__ __forceinline__ float evalg(const float2 x[2][NPAIR],
                                       const float2 w[NPAIR],
                                       float lam0, float lam1, bool hb) {
    float2 m0 = make_float2(-lam0, -lam0);
    float2 m1 = make_float2(-lam1, -lam1);
    float2 s0 = make_float2(0.f, 0.f);
    float2 s1 = make_float2(0.f, 0.f);
#pragma unroll
    for (int j = 0; j < NPAIR; j++) {
        float2 z0 = clip01(fma2(m0, w[j], x[0][j]));
        float2 z1 = clip01(fma2(m1, w[j], x[1][j]));
        s0 = fma2(z0, w[j], s0);
        s1 = fma2(z1, w[j], s1);
    }
    return red8_split(s0.x + s0.y, s1.x + s1.y, hb) - CAPC;
}

// x = clip(x - lam*w, 0, 1); accumulate this lane's ||x||^2 partials.
__device__ __forceinline__ void applyp(float2 x[2][NPAIR],
                                       const float2 w[NPAIR],
                                       float lam0, float lam1,
                                       float& na0, float& na1) {
    float2 m0 = make_float2(-lam0, -lam0);
    float2 m1 = make_float2(-lam1, -lam1);
    float2 a0 = make_float2(0.f, 0.f);
    float2 a1 = make_float2(0.f, 0.f);
#pragma unroll
    for (int j = 0; j < NPAIR; j++) {
        x[0][j] = clip01(fma2(m0, w[j], x[0][j]));
        x[1][j] = clip01(fma2(m1, w[j], x[1][j]));
        a0 = fma2(x[0][j], x[0][j], a0);
        a1 = fma2(x[1][j], x[1][j], a1);
    }
    na0 = a0.x + a0.y;
    na1 = a1.x + a1.y;
}

__global__ void __launch_bounds__(64)
cvx_knapsack_kernel(const float* __restrict__ costs,
                    const float* __restrict__ wg,
                    float* __restrict__ out) {
    int tid  = blockIdx.x * blockDim.x + threadIdx.x;
    int q    = tid & 7;          // lane within the row's 8-lane group
    int pair = tid >> 3;         // handles rows 2*pair, 2*pair+1
    int row0 = pair * 2;
    if (row0 >= BROWS) return;
    bool hb = (q & 4) != 0;      // my scalar state: row1 if hb else row0

    float2 w[NPAIR], ec[2][NPAIR], x[2][NPAIR];

    const float4* wp = reinterpret_cast<const float4*>(wg + q * IPT);
#pragma unroll
    for (int j = 0; j < NPAIR / 2; j++) {
        float4 wv = wp[j];
        w[2*j]     = make_float2(wv.x, wv.y);
        w[2*j + 1] = make_float2(wv.z, wv.w);
    }

#pragma unroll
    for (int r = 0; r < 2; r++) {
        const float4* cp = reinterpret_cast<const float4*>(
            costs + (row0 + r) * NITEMS + q * IPT);
#pragma unroll
        for (int j = 0; j < NPAIR / 2; j++) {
            float4 cv = cp[j];
            x[r][2*j].x   = __saturatef(cv.x);      // clip(c, 0, 1)
            x[r][2*j].y   = __saturatef(cv.y);
            x[r][2*j+1].x = __saturatef(cv.z);
            x[r][2*j+1].y = __saturatef(cv.w);
            ec[r][2*j]   = make_float2(ETAC * cv.x, ETAC * cv.y);
            ec[r][2*j+1] = make_float2(ETAC * cv.z, ETAC * cv.w);
        }
    }

    // Per-lane scalar state for MY row.
    float lam_m = 0.f, rd_m = 1.0f / 1000.0f;       // ~1/Sum_interior w^2
    float lamp_m = 0.f, fp_m = 0.f;
    float na0, na1;

    // Cold projection: NIT0 bracketed secant iterations.
    {
        float lo = 0.f, hi = HI0;
#pragma unroll 1
        for (int it = 0; it < NIT0; it++) {
            float lam_o = __shfl_xor_sync(0xffffffffu, lam_m, 4);
            float f = evalg(x, w, hb ? lam_o : lam_m, hb ? lam_m : lam_o, hb);
            bool over = f > 0.f;
            lo = over ? lam_m : lo;
            hi = over ? hi    : lam_m;
            if (it > 0) {
                float rds = __fdividef(lam_m - lamp_m, fp_m - f);
                rd_m = (rds > 0.f && rds < 1e12f) ? rds : rd_m;
            }
            lamp_m = lam_m;
            fp_m   = f;
            float ln = fmaf(f, rd_m, lam_m);
            ln = fmaxf(ln, lo);                     // NaN-safe clamps
            ln = fminf(ln, hi);
            lam_m = ln;
        }
        float lam_o = __shfl_xor_sync(0xffffffffu, lam_m, 4);
        applyp(x, w, hb ? lam_o : lam_m, hb ? lam_m : lam_o, na0, na1);
    }

    // 120 PGD steps: x = project(k*x + eta*c), k = 1 - eta/||x||  (MU = 1)
#pragma unroll 1
    for (int t = 0; t < NPGD; t++) {
        // Norm of my row (partials from the previous apply), lane-parallel.
        float nm  = red8_split(na0, na1, hb);
        float inv = rsqrtf(nm + 1e-12f);
        float k_m = fmaf(-ETAC, inv, 1.0f);
        float k_o = __shfl_xor_sync(0xffffffffu, k_m, 4);
        float kr0 = hb ? k_o : k_m;
        float kr1 = hb ? k_m : k_o;
        float2 k0 = make_float2(kr0, kr0);
        float2 k1 = make_float2(kr1, kr1);
#pragma unroll
        for (int j = 0; j < NPAIR; j++) {
            x[0][j] = fma2(k0, x[0][j], ec[0][j]);
            x[1][j] = fma2(k1, x[1][j], ec[1][j]);
        }

        // Warm projection: NIT=2 bracketed secant iterations (same-g secant).
        float lo = 0.f, hi = HI0;
#pragma unroll
        for (int it = 0; it < NIT; it++) {
            float lam_o = __shfl_xor_sync(0xffffffffu, lam_m, 4);
            float f = evalg(x, w, hb ? lam_o : lam_m, hb ? lam_m : lam_o, hb);
            bool over = f > 0.f;
            lo = over ? lam_m : lo;
            hi = over ? hi    : lam_m;
            if (it > 0) {       // within-projection secant (same g!)
                float rds = __fdividef(lam_m - lamp_m, fp_m - f);
                rd_m = (rds > 0.f && rds < 1e12f) ? rds : rd_m;
            }
            lamp_m = lam_m;
            fp_m   = f;
            float ln = fmaf(f, rd_m, lam_m);
            ln = fmaxf(ln, lo);
            ln = fminf(ln, hi);
            lam_m = ln;
        }
        float lam_o = __shfl_xor_sync(0xffffffffu, lam_m, 4);
        applyp(x, w, hb ? lam_o : lam_m, hb ? lam_m : lam_o, na0, na1);
    }

#pragma unroll
    for (int r = 0; r < 2; r++) {
        float4* op = reinterpret_cast<float4*>(out + (row0 + r) * NITEMS + q * IPT);
#pragma unroll
        for (int j = 0; j < NPAIR / 2; j++) {
            float4 v;
            v.x = x[r][2*j].x;     v.y = x[r][2*j].y;
            v.z = x[r][2*j + 1].x; v.w = x[r][2*j + 1].y;
            op[j] = v;
        }
    }
}

extern "C" void kernel_launch(void* const* d_in, const int* in_sizes, int n_in,
                              void* d_out, int out_size) {
    const float* costs = (const float*)d_in[0];
    const float* wts   = (const float*)d_in[1];
    if (n_in >= 2 && in_sizes[0] == NITEMS) {   // guard against input order swap
        costs = (const float*)d_in[1];
        wts   = (const float*)d_in[0];
    }
    float* out = (float*)d_out;

    const int threads = 64;
    const int total   = (BROWS / 2) * TPR;                 // 65536 threads
    const int blocks  = (total + threads - 1) / threads;   // 1024 blocks
    cvx_knapsack_kernel<<<blocks, threads>>>(costs, wts, out);
}